// round 15
// baseline (speedup 1.0000x reference)
#include <cuda_runtime.h>
#include <cuda_bf16.h>
#include <math.h>

#define NN 100000
#define NE 20000
#define NP 3200000
#define D  512
#define NREP 4                    // edge accumulator replicas
#define NCHUNK (NP / 4)           // 800000 int4 pair chunks

#define L_GRID  1563              // ceil(100000 / 64)
#define L_THR   128

// ---------------- scratch (device globals; no allocation) ----------------
__device__ float4 g_m[NN];            // gelu(x @ Wmsg^T)         [N,4]
__device__ float4 g_u[NN];            // x @ Wupd^T + b           [N,4]
__device__ float4 g_ef[NE];           // edge means

// zero-initialized accumulators, packed so ONE memset clears them all (3.6MB)
struct Scratch {
    float4 esum[NREP * NE];           // 1.28 MB
    float  ecnt[NREP * NE];           // 0.32 MB
    float4 nsum[NN];                  // 1.6 MB
    float  ncnt[NN];                  // 0.4 MB
};
__device__ Scratch g_s;

__device__ __forceinline__ float gelu_exact(float v) {
    return 0.5f * v * (1.0f + erff(v * 0.70710678118654752f));
}

// tf32 helpers: hi = round-to-nearest tf32 of v (bit pattern reinterpretable
// as f32 with low mantissa bits cleared); lo = residual, re-rounded on use.
__device__ __forceinline__ unsigned int to_tf32(float v) {
    unsigned int r;
    asm("cvt.rna.tf32.f32 %0, %1;" : "=r"(r) : "f"(v));
    return r;
}

__device__ __forceinline__ void mma_tf32(
    float& d0, float& d1, float& d2, float& d3,
    unsigned int a0, unsigned int a1, unsigned int a2, unsigned int a3,
    unsigned int b0, unsigned int b1)
{
    asm volatile(
        "mma.sync.aligned.m16n8k8.row.col.f32.tf32.tf32.f32 "
        "{%0,%1,%2,%3}, {%4,%5,%6,%7}, {%8,%9}, {%0,%1,%2,%3};\n"
        : "+f"(d0), "+f"(d1), "+f"(d2), "+f"(d3)
        : "r"(a0), "r"(a1), "r"(a2), "r"(a3), "r"(b0), "r"(b1));
}

// ---------------- kernel 1: tensor-core dual GEMM (3xTF32) + GELU + counts ----------------
// 1563 CTAs x 128 thr (4 warps). CTA = 64 rows x 8 outputs, K=512 in 8 chunks
// of 64. Warp w owns rows 16w..16w+15 via mma.m16n8k8 (N=8 = all outputs).
// 3xTF32: D += Ah*Bh + Al*Bh + Ah*Bl  (fp32-grade precision, ~1e-6).
// x smem stride 68 and W smem stride 516 kill LDS bank conflicts.
// Phase B: balanced pair counting (4 int4 chunks per thread, grid-stride).
__global__ __launch_bounds__(L_THR) void k_linear(
    const float4* __restrict__ x4,      // [N, 128] float4
    const float4* __restrict__ wmsg4,   // [4, 128]
    const float4* __restrict__ wupd4,   // [4, 128]
    const float*  __restrict__ b_upd,   // [4]
    const int4*   __restrict__ pn4,
    const int4*   __restrict__ pe4)
{
    __shared__ float xs[64 * 68];       // 64 rows x 64 cols, stride 68
    __shared__ float ws[8 * 516];       // 8 outputs x 512 k, stride 516

    int t    = threadIdx.x;
    int warp = t >> 5;
    int lane = t & 31;
    int cta_row0 = blockIdx.x * 64;

    // ---- stage W (Wmsg -> outputs 0-3, Wupd -> 4-7), one time ----
    for (int idx = t; idx < 512; idx += L_THR) {       // 512 float4 = Wmsg
        int n = idx >> 7, c4 = idx & 127;
        float4 v = wmsg4[idx];
        *reinterpret_cast<float4*>(&ws[n * 516 + c4 * 4]) = v;
    }
    for (int idx = t; idx < 512; idx += L_THR) {       // Wupd
        int n = idx >> 7, c4 = idx & 127;
        float4 v = wupd4[idx];
        *reinterpret_cast<float4*>(&ws[(n + 4) * 516 + c4 * 4]) = v;
    }

    float d0 = 0.f, d1 = 0.f, d2 = 0.f, d3 = 0.f;

    int fr_row = lane >> 2;             // 0..7
    int fr_c   = lane & 3;              // 0..3

    for (int kc = 0; kc < 8; kc++) {
        __syncthreads();
        // stage x chunk: 64 rows x 16 float4 (cols kc*64..kc*64+63)
        #pragma unroll
        for (int i = 0; i < 8; i++) {
            int idx = t + i * L_THR;    // 0..1023
            int row = idx >> 4, c4 = idx & 15;
            int grow = cta_row0 + row;
            if (grow > NN - 1) grow = NN - 1;
            float4 v = x4[(size_t)grow * 128 + kc * 16 + c4];
            *reinterpret_cast<float4*>(&xs[row * 68 + c4 * 4]) = v;
        }
        __syncthreads();

        #pragma unroll
        for (int s = 0; s < 8; s++) {
            int ko = s * 8;
            // A fragments (row-major 16x8): rows fr_row, fr_row+8; cols fr_c, fr_c+4
            int rbase = warp * 16;
            float va0 = xs[(rbase + fr_row) * 68 + ko + fr_c];
            float va1 = xs[(rbase + fr_row + 8) * 68 + ko + fr_c];
            float va2 = xs[(rbase + fr_row) * 68 + ko + fr_c + 4];
            float va3 = xs[(rbase + fr_row + 8) * 68 + ko + fr_c + 4];
            // B fragments (col-major 8k x 8n): k = fr_c, fr_c+4; n = fr_row
            int kgl = kc * 64 + ko;
            float vb0 = ws[fr_row * 516 + kgl + fr_c];
            float vb1 = ws[fr_row * 516 + kgl + fr_c + 4];

            unsigned int ah0 = to_tf32(va0), ah1 = to_tf32(va1);
            unsigned int ah2 = to_tf32(va2), ah3 = to_tf32(va3);
            unsigned int bh0 = to_tf32(vb0), bh1 = to_tf32(vb1);
            unsigned int al0 = to_tf32(va0 - __uint_as_float(ah0));
            unsigned int al1 = to_tf32(va1 - __uint_as_float(ah1));
            unsigned int al2 = to_tf32(va2 - __uint_as_float(ah2));
            unsigned int al3 = to_tf32(va3 - __uint_as_float(ah3));
            unsigned int bl0 = to_tf32(vb0 - __uint_as_float(bh0));
            unsigned int bl1 = to_tf32(vb1 - __uint_as_float(bh1));

            mma_tf32(d0, d1, d2, d3, al0, al1, al2, al3, bh0, bh1); // Al*Bh
            mma_tf32(d0, d1, d2, d3, ah0, ah1, ah2, ah3, bl0, bl1); // Ah*Bl
            mma_tf32(d0, d1, d2, d3, ah0, ah1, ah2, ah3, bh0, bh1); // Ah*Bh
        }
    }

    // ---- epilogue: D frags -> smem (reuse xs) -> g_m / g_u ----
    __syncthreads();                    // xs no longer needed for input
    {
        int rl = warp * 16 + fr_row;    // local row of c0/c1
        int c  = fr_c * 2;              // cols 2j, 2j+1
        xs[rl * 8 + c] = d0;
        xs[rl * 8 + c + 1] = d1;
        xs[(rl + 8) * 8 + c] = d2;
        xs[(rl + 8) * 8 + c + 1] = d3;
    }
    __syncthreads();
    if (t < 64) {
        int grow = cta_row0 + t;
        if (grow < NN) {
            float h0 = xs[t * 8 + 0], h1 = xs[t * 8 + 1];
            float h2 = xs[t * 8 + 2], h3 = xs[t * 8 + 3];
            float u0 = xs[t * 8 + 4], u1 = xs[t * 8 + 5];
            float u2 = xs[t * 8 + 6], u3 = xs[t * 8 + 7];
            g_m[grow] = make_float4(gelu_exact(h0), gelu_exact(h1),
                                    gelu_exact(h2), gelu_exact(h3));
            g_u[grow] = make_float4(u0 + __ldg(&b_upd[0]), u1 + __ldg(&b_upd[1]),
                                    u2 + __ldg(&b_upd[2]), u3 + __ldg(&b_upd[3]));
        }
    }

    // ---- Phase B: multiplicity counts (grid-stride, balanced) ----
    cudaGridDependencySynchronize();          // scratch memset must be done
    int tid = blockIdx.x * L_THR + t;         // 200064 threads
    for (int idx = tid; idx < NCHUNK; idx += L_GRID * L_THR) {
        int4 n4 = __ldg(&pn4[idx]);
        int4 e4 = __ldg(&pe4[idx]);
        int erep = (t & (NREP - 1)) * NE;
        #pragma unroll
        for (int j = 0; j < 4; j++) {
            int n = (j == 0) ? n4.x : (j == 1) ? n4.y : (j == 2) ? n4.z : n4.w;
            int e = (j == 0) ? e4.x : (j == 1) ? e4.y : (j == 2) ? e4.z : e4.w;
            atomicAdd(&g_s.ecnt[erep + e], 1.0f);
            atomicAdd(&g_s.ncnt[n], 1.0f);
        }
    }
}

// ---------------- kernel 2: pair scatter #1 (node msgs -> edge sums) ----------------
__global__ __launch_bounds__(256) void k_scatter_edges(
    const int4* __restrict__ pn4,
    const int4* __restrict__ pe4)
{
    int t = blockIdx.x * blockDim.x + threadIdx.x;
    int4 n4 = __ldg(&pn4[t]);
    int4 e4 = __ldg(&pe4[t]);
    int erep = (threadIdx.x & (NREP - 1)) * NE;

    cudaGridDependencySynchronize();          // wait: g_m ready

    #pragma unroll
    for (int j = 0; j < 4; j++) {
        int n = (j == 0) ? n4.x : (j == 1) ? n4.y : (j == 2) ? n4.z : n4.w;
        int e = (j == 0) ? e4.x : (j == 1) ? e4.y : (j == 2) ? e4.z : e4.w;
        float4 mv = g_m[n];
        atomicAdd(&g_s.esum[erep + e], mv);      // RED.128 (only atomic here)
    }
}

// ---------------- kernel 3: edge mean — 4 threads per edge ----------------
__global__ void k_edge_mean() {
    cudaGridDependencySynchronize();
    int gid = blockIdx.x * blockDim.x + threadIdx.x;
    int e = gid >> 2;
    int r = gid & 3;
    if (e >= NE) return;
    float4 v = g_s.esum[r * NE + e];
    float cnt = g_s.ecnt[r * NE + e];
    #pragma unroll
    for (int off = 2; off > 0; off >>= 1) {
        v.x += __shfl_xor_sync(0xFFFFFFFFu, v.x, off);
        v.y += __shfl_xor_sync(0xFFFFFFFFu, v.y, off);
        v.z += __shfl_xor_sync(0xFFFFFFFFu, v.z, off);
        v.w += __shfl_xor_sync(0xFFFFFFFFu, v.w, off);
        cnt += __shfl_xor_sync(0xFFFFFFFFu, cnt, off);
    }
    if (r == 0) {
        float inv = 1.0f / fmaxf(cnt, 1.0f);
        g_ef[e] = make_float4(v.x * inv, v.y * inv, v.z * inv, v.w * inv);
    }
}

// ---------------- kernel 4: pair scatter #2 (edge means -> node sums) ----------------
__global__ __launch_bounds__(256) void k_scatter_nodes(
    const int4* __restrict__ pn4,
    const int4* __restrict__ pe4)
{
    int t = blockIdx.x * blockDim.x + threadIdx.x;
    int4 n4 = __ldg(&pn4[t]);
    int4 e4 = __ldg(&pe4[t]);

    cudaGridDependencySynchronize();          // wait: g_ef ready

    #pragma unroll
    for (int j = 0; j < 4; j++) {
        int n = (j == 0) ? n4.x : (j == 1) ? n4.y : (j == 2) ? n4.z : n4.w;
        int e = (j == 0) ? e4.x : (j == 1) ? e4.y : (j == 2) ? e4.z : e4.w;
        float4 ev = g_ef[e];
        atomicAdd(&g_s.nsum[n], ev);             // RED.128 (only atomic here)
    }
}

// ---------------- kernel 5: update + log_softmax ----------------
__global__ void k_final(float4* __restrict__ out4) {
    cudaGridDependencySynchronize();
    int i = blockIdx.x * blockDim.x + threadIdx.x;
    if (i >= NN) return;
    float4 u = g_u[i];
    float4 s = g_s.nsum[i];
    float inv = 1.0f / fmaxf(g_s.ncnt[i], 1.0f);
    float h0 = gelu_exact(u.x + s.x * inv);
    float h1 = gelu_exact(u.y + s.y * inv);
    float h2 = gelu_exact(u.z + s.z * inv);
    float h3 = gelu_exact(u.w + s.w * inv);
    float mx = fmaxf(fmaxf(h0, h1), fmaxf(h2, h3));
    float lse = mx + logf(expf(h0 - mx) + expf(h1 - mx)
                        + expf(h2 - mx) + expf(h3 - mx));
    out4[i] = make_float4(h0 - lse, h1 - lse, h2 - lse, h3 - lse);
}

// ---------------- PDL launch helper ----------------
template <typename K, typename... Args>
static void launch_pdl(K kernel, dim3 grid, dim3 block, Args... args) {
    cudaLaunchConfig_t cfg = {};
    cfg.gridDim = grid;
    cfg.blockDim = block;
    cfg.dynamicSmemBytes = 0;
    cfg.stream = 0;
    cudaLaunchAttribute attr[1];
    attr[0].id = cudaLaunchAttributeProgrammaticStreamSerialization;
    attr[0].val.programmaticStreamSerializationAllowed = 1;
    cfg.attrs = attr;
    cfg.numAttrs = 1;
    cudaLaunchKernelEx(&cfg, kernel, args...);
}

// ---------------- launch ----------------
extern "C" void kernel_launch(void* const* d_in, const int* in_sizes, int n_in,
                              void* d_out, int out_size) {
    const float* x         = (const float*)d_in[0];
    const int*   pair_node = (const int*)d_in[1];
    const int*   pair_edge = (const int*)d_in[2];
    const float* W_msg     = (const float*)d_in[3];
    const float* W_upd     = (const float*)d_in[4];
    const float* b_upd     = (const float*)d_in[5];
    float4* out4 = (float4*)d_out;

    static void* scratch_ptr = nullptr;
    if (!scratch_ptr) cudaGetSymbolAddress(&scratch_ptr, g_s);
    cudaMemsetAsync(scratch_ptr, 0, sizeof(Scratch));

    launch_pdl(k_linear, dim3(L_GRID), dim3(L_THR),
               (const float4*)x, (const float4*)W_msg, (const float4*)W_upd,
               b_upd, (const int4*)pair_node, (const int4*)pair_edge);

    launch_pdl(k_scatter_edges, dim3(NP / 4 / 256), dim3(256),
               (const int4*)pair_node, (const int4*)pair_edge);

    launch_pdl(k_edge_mean, dim3((NE * 4 + 255) / 256), dim3(256));

    launch_pdl(k_scatter_nodes, dim3(NP / 4 / 256), dim3(256),
               (const int4*)pair_node, (const int4*)pair_edge);

    launch_pdl(k_final, dim3((NN + 255) / 256), dim3(256), out4);
}